// round 4
// baseline (speedup 1.0000x reference)
#include <cuda_runtime.h>
#include <cstdint>

#define BB 32
#define NN 16384
#define DD 64

// Scratch (no allocations allowed)
__device__ float    g_rowsum[BB];
__device__ int      g_k[BB];
__device__ unsigned g_visbits[BB * (NN / 32)];   // 64KB visibility bitmask
__device__ unsigned g_done;

// ---------------------------------------------------------------------------
// Kernel A: one CTA per row. Computes ws keys (registers + smem shadow),
// exact 4x8-bit radix select from registers, emits visibility bitmask AND
// the visible-float output slice (overlaps with other rows' compute).
// ---------------------------------------------------------------------------
__global__ void __launch_bounds__(1024, 1) k_keys_select(
    const float* __restrict__ u_g, const float* __restrict__ lpt,
    const float* __restrict__ lph, const float* __restrict__ lpw,
    const float* __restrict__ u_k, float* __restrict__ out, int out_size)
{
    extern __shared__ uint32_t skeys[];   // NN words (64KB), for rare tie path
    __shared__ unsigned hist[256];
    __shared__ unsigned suf[256];
    __shared__ uint32_t s_prefix;
    __shared__ int s_krem, s_eqcnt;

    int b = blockIdx.x;
    int tid = threadIdx.x;

    if (tid == 0) {
        g_rowsum[b] = 0.f;
        if (b == 0) g_done = 0u;
    }

    // k per row: rates = (u_k + b/31) % 1 ; k = clip(int(N*rates), 1, N-1)
    float r = u_k[0] + (float)b * (1.0f / 31.0f);
    r = r - floorf(r);
    int k = (int)(16384.0f * r);
    k = k < 1 ? 1 : (k > NN - 1 ? NN - 1 : k);
    if (tid == 0) g_k[b] = k;

    // Element i = s*1024 + tid  =>  t = s, h = tid>>5, w = tid&31
    float lph_v = lph[b * 32 + (tid >> 5)];
    float lpw_v = lpw[b * 32 + (tid & 31)];
    const float* __restrict__ ug = u_g + ((size_t)b << 14);
    const float* __restrict__ lt = lpt + b * 16;

    uint32_t key[16];
    #pragma unroll
    for (int s = 0; s < 16; s++) {
        float u = ug[s * 1024 + tid];
        float g = -logf(-logf(u));
        float m = (lt[s] + lph_v) + lpw_v;     // same association as reference
        float ws = g + m;
        uint32_t bits = __float_as_uint(ws);
        uint32_t kk = (bits & 0x80000000u) ? ~bits : (bits | 0x80000000u);
        key[s] = kk;
        skeys[s * 1024 + tid] = kk;
    }
    __syncthreads();

    // 4-pass radix select on register-resident keys
    uint32_t prefix = 0, pmask = 0;
    int krem = k;
    for (int pass = 0; pass < 4; pass++) {
        int shift = 24 - 8 * pass;
        if (tid < 256) hist[tid] = 0;
        __syncthreads();
        #pragma unroll
        for (int s = 0; s < 16; s++) {
            uint32_t kk = key[s];
            if ((kk & pmask) == prefix)
                atomicAdd(&hist[(kk >> shift) & 255u], 1u);
        }
        __syncthreads();
        if (tid < 256) suf[tid] = hist[tid];
        __syncthreads();
        // inclusive suffix sums (Hillis-Steele)
        for (int d = 1; d < 256; d <<= 1) {
            unsigned v = 0;
            if (tid < 256) { v = suf[tid]; if (tid + d < 256) v += suf[tid + d]; }
            __syncthreads();
            if (tid < 256) suf[tid] = v;
            __syncthreads();
        }
        if (tid < 256) {
            int above = (int)(suf[tid] - hist[tid]);   // strictly larger keys
            if (above < krem && krem <= (int)suf[tid]) {
                s_prefix = prefix | ((uint32_t)tid << shift);
                s_krem = krem - above;
                if (pass == 3) s_eqcnt = (int)hist[tid];
            }
        }
        __syncthreads();
        prefix = s_prefix;
        krem = s_krem;
        pmask |= (0xFFu << shift);
        __syncthreads();
    }

    uint32_t thr = prefix;
    int eqcnt = s_eqcnt;

    bool emit_vis = (out_size >= BB * NN);
    int vis_off = (out_size > BB * NN) ? 1 : 0;      // loss slot first
    float* __restrict__ out_vis = out + vis_off + ((size_t)b << 14);

    // Visibility -> bitmask + visible floats
    #pragma unroll
    for (int s = 0; s < 16; s++) {
        uint32_t kk = key[s];
        bool vis;
        if (kk > thr) vis = true;
        else if (kk < thr) vis = false;
        else if (eqcnt <= krem) vis = true;          // all ties fit in top-k
        else {
            // rare tie path: stable rank by index among equals (from smem)
            int n = s * 1024 + tid;
            int cnt = 0;
            for (int i = 0; i < n; i++) cnt += (skeys[i] == thr);
            vis = cnt < krem;
        }
        unsigned m = __ballot_sync(0xffffffffu, vis);
        if ((tid & 31) == 0)
            g_visbits[(b << 9) + ((s * 1024 + tid) >> 5)] = m;
        if (emit_vis)
            out_vis[s * 1024 + tid] = vis ? 1.0f : 0.0f;
    }
}

// ---------------------------------------------------------------------------
// Kernel B: full-chip masked score reduction. Explicit 32-wide load batch
// (float2 v[32], predicated) -> MLP ~32/warp, then 8-way accumulate.
// Last block computes the rate-corrected loss.
// ---------------------------------------------------------------------------
__global__ void __launch_bounds__(256) k_mask_final(
    const float* __restrict__ score, float* __restrict__ out, int out_size)
{
    __shared__ float ssum[8];
    __shared__ bool slast;
    int base = blockIdx.x * 256;
    int b = base >> 14;
    int warp = threadIdx.x >> 5, lane = threadIdx.x & 31;
    int tok0 = base + warp * 32;

    unsigned visword = g_visbits[tok0 >> 5];

    // Warp's 32 token rows; each row = 32 float2 (256B), this lane's pair.
    const float2* __restrict__ rows =
        (const float2*)score + (((size_t)tok0) << 5) + lane;

    // Phase 1: issue all 32 predicated loads (independent -> batched by ptxas)
    float2 v[32];
    #pragma unroll
    for (int j = 0; j < 32; j++) {
        v[j] = make_float2(0.f, 0.f);
        if (!((visword >> j) & 1u)) v[j] = rows[(size_t)j << 5];
    }

    // Phase 2: accumulate with 8 rotating accumulators
    float a[8];
    #pragma unroll
    for (int i = 0; i < 8; i++) a[i] = 0.f;
    #pragma unroll
    for (int j = 0; j < 32; j++) a[j & 7] += v[j].x + v[j].y;
    float acc = ((a[0] + a[1]) + (a[2] + a[3])) + ((a[4] + a[5]) + (a[6] + a[7]));

    #pragma unroll
    for (int o = 16; o; o >>= 1) acc += __shfl_down_sync(0xffffffffu, acc, o);
    if (lane == 0) ssum[warp] = acc;
    __syncthreads();
    if (threadIdx.x == 0) {
        float t = 0.f;
        #pragma unroll
        for (int i = 0; i < 8; i++) t += ssum[i];
        atomicAdd(&g_rowsum[b], t);
        __threadfence();
        unsigned old = atomicAdd(&g_done, 1u);
        slast = (old == gridDim.x - 1);
    }
    __syncthreads();
    if (slast && threadIdx.x < 32) {
        __threadfence();
        float w = g_rowsum[threadIdx.x] *
                  (16384.0f / (float)(NN - g_k[threadIdx.x]));
        #pragma unroll
        for (int o = 16; o; o >>= 1) w += __shfl_down_sync(0xffffffffu, w, o);
        if (threadIdx.x == 0 && out_size != BB * NN)
            out[0] = w / 33554432.0f;                // B*N*D
    }
}

extern "C" void kernel_launch(void* const* d_in, const int* in_sizes, int n_in,
                              void* d_out, int out_size) {
    const float* u_g   = (const float*)d_in[0];
    const float* lpt   = (const float*)d_in[1];
    const float* lph   = (const float*)d_in[2];
    const float* lpw   = (const float*)d_in[3];
    const float* u_k   = (const float*)d_in[4];
    const float* score = (const float*)d_in[5];
    float* out = (float*)d_out;

    cudaFuncSetAttribute(k_keys_select,
                         cudaFuncAttributeMaxDynamicSharedMemorySize, 65536);

    k_keys_select<<<BB, 1024, 65536>>>(u_g, lpt, lph, lpw, u_k, out, out_size);
    k_mask_final<<<BB * NN / 256, 256>>>(score, out, out_size);
}

// round 5
// speedup vs baseline: 1.1449x; 1.1449x over previous
#include <cuda_runtime.h>
#include <cstdint>

#define BB 32
#define NN 16384
#define DD 64

// Scratch (no allocations allowed)
__device__ uint32_t g_keys[BB * NN];             // 2MB monotonic keys
__device__ float    g_rowsum[BB];
__device__ int      g_k[BB];
__device__ unsigned g_visbits[BB * (NN / 32)];   // 64KB visibility bitmask
__device__ unsigned g_done;

// ---------------------------------------------------------------------------
// Kernel A1: full-chip key computation. ws = gumbel + marginals -> monotonic
// uint32 key. 2048 CTAs so the double-logf cost spreads over all SMs.
// ---------------------------------------------------------------------------
__global__ void __launch_bounds__(256) k_keys(
    const float* __restrict__ u_g, const float* __restrict__ lpt,
    const float* __restrict__ lph, const float* __restrict__ lpw)
{
    int idx = blockIdx.x * 256 + threadIdx.x;
    if (idx < BB) g_rowsum[idx] = 0.f;
    if (idx == 0) g_done = 0u;
    int b = idx >> 14;
    int n = idx & (NN - 1);
    int t = n >> 10;
    int h = (n >> 5) & 31;
    int w = n & 31;
    float u = u_g[idx];
    float g = -logf(-logf(u));
    float m = (lpt[b * 16 + t] + lph[b * 32 + h]) + lpw[b * 32 + w];  // ref assoc
    float ws = g + m;
    uint32_t bits = __float_as_uint(ws);
    g_keys[idx] = (bits & 0x80000000u) ? ~bits : (bits | 0x80000000u);
}

// ---------------------------------------------------------------------------
// Kernel A2: one CTA per row. Loads keys into registers (+smem shadow for the
// rare tie path), exact 4x8-bit radix select, emits visibility bitmask.
// ---------------------------------------------------------------------------
__global__ void __launch_bounds__(1024, 1) k_select(const float* __restrict__ u_k)
{
    extern __shared__ uint32_t skeys[];   // NN words (64KB)
    __shared__ unsigned hist[256];
    __shared__ unsigned suf[256];
    __shared__ uint32_t s_prefix;
    __shared__ int s_krem, s_eqcnt;

    int b = blockIdx.x;
    int tid = threadIdx.x;

    // k per row: rates = (u_k + b/31) % 1 ; k = clip(int(N*rates), 1, N-1)
    float r = u_k[0] + (float)b * (1.0f / 31.0f);
    r = r - floorf(r);
    int k = (int)(16384.0f * r);
    k = k < 1 ? 1 : (k > NN - 1 ? NN - 1 : k);
    if (tid == 0) g_k[b] = k;

    const uint32_t* __restrict__ keys = g_keys + ((size_t)b << 14);
    uint32_t key[16];
    #pragma unroll
    for (int s = 0; s < 16; s++) {
        uint32_t kk = keys[s * 1024 + tid];
        key[s] = kk;
        skeys[s * 1024 + tid] = kk;
    }
    __syncthreads();

    // 4-pass radix select on register-resident keys
    uint32_t prefix = 0, pmask = 0;
    int krem = k;
    for (int pass = 0; pass < 4; pass++) {
        int shift = 24 - 8 * pass;
        if (tid < 256) hist[tid] = 0;
        __syncthreads();
        #pragma unroll
        for (int s = 0; s < 16; s++) {
            uint32_t kk = key[s];
            if ((kk & pmask) == prefix)
                atomicAdd(&hist[(kk >> shift) & 255u], 1u);
        }
        __syncthreads();
        if (tid < 256) suf[tid] = hist[tid];
        __syncthreads();
        for (int d = 1; d < 256; d <<= 1) {       // inclusive suffix sums
            unsigned v = 0;
            if (tid < 256) { v = suf[tid]; if (tid + d < 256) v += suf[tid + d]; }
            __syncthreads();
            if (tid < 256) suf[tid] = v;
            __syncthreads();
        }
        if (tid < 256) {
            int above = (int)(suf[tid] - hist[tid]);   // strictly larger keys
            if (above < krem && krem <= (int)suf[tid]) {
                s_prefix = prefix | ((uint32_t)tid << shift);
                s_krem = krem - above;
                if (pass == 3) s_eqcnt = (int)hist[tid];
            }
        }
        __syncthreads();
        prefix = s_prefix;
        krem = s_krem;
        pmask |= (0xFFu << shift);
        __syncthreads();
    }

    uint32_t thr = prefix;
    int eqcnt = s_eqcnt;

    // Visibility -> bitmask (one ballot word per 32 consecutive tokens)
    #pragma unroll
    for (int s = 0; s < 16; s++) {
        uint32_t kk = key[s];
        bool vis;
        if (kk > thr) vis = true;
        else if (kk < thr) vis = false;
        else if (eqcnt <= krem) vis = true;          // all ties fit in top-k
        else {
            // rare tie path: stable rank by index among equals (from smem)
            int n = s * 1024 + tid;
            int cnt = 0;
            for (int i = 0; i < n; i++) cnt += (skeys[i] == thr);
            vis = cnt < krem;
        }
        unsigned m = __ballot_sync(0xffffffffu, vis);
        if ((tid & 31) == 0)
            g_visbits[(b << 9) + ((s * 1024 + tid) >> 5)] = m;
    }
}

// ---------------------------------------------------------------------------
// Kernel B: full-chip masked score reduction. R3 loop shape (regs~32, high
// occupancy, 4-wide predicated loads). Blocks interleaved round-robin over
// rows (b = g & 31) so every wave carries the average load mix.
// Last block computes the rate-corrected loss.
// ---------------------------------------------------------------------------
__global__ void __launch_bounds__(256) k_mask_final(
    const float* __restrict__ score, float* __restrict__ out, int out_size)
{
    __shared__ float ssum[8];
    __shared__ bool slast;
    int g = blockIdx.x;
    int b = g & 31;
    int chunk = g >> 5;                              // 0..63
    int warp = threadIdx.x >> 5, lane = threadIdx.x & 31;
    int tok0 = (b << 14) + chunk * 256 + warp * 32;

    unsigned visword = g_visbits[tok0 >> 5];

    if (out_size >= BB * NN) {
        int off = (out_size > BB * NN) ? 1 : 0;      // loss slot first
        out[off + tok0 + lane] = ((visword >> lane) & 1u) ? 1.0f : 0.0f;
    }

    // Warp's 32 token rows; each row = 32 float2 (256B), this lane's pair.
    const float2* __restrict__ rows =
        (const float2*)score + (((size_t)tok0) << 5) + lane;

    float a0 = 0.f, a1 = 0.f, a2 = 0.f, a3 = 0.f;
    #pragma unroll
    for (int j = 0; j < 32; j += 4) {
        float2 v0 = make_float2(0.f, 0.f), v1 = v0, v2 = v0, v3 = v0;
        if (!((visword >> (j + 0)) & 1u)) v0 = rows[(size_t)(j + 0) << 5];
        if (!((visword >> (j + 1)) & 1u)) v1 = rows[(size_t)(j + 1) << 5];
        if (!((visword >> (j + 2)) & 1u)) v2 = rows[(size_t)(j + 2) << 5];
        if (!((visword >> (j + 3)) & 1u)) v3 = rows[(size_t)(j + 3) << 5];
        a0 += v0.x + v0.y;
        a1 += v1.x + v1.y;
        a2 += v2.x + v2.y;
        a3 += v3.x + v3.y;
    }
    float acc = (a0 + a1) + (a2 + a3);
    #pragma unroll
    for (int o = 16; o; o >>= 1) acc += __shfl_down_sync(0xffffffffu, acc, o);
    if (lane == 0) ssum[warp] = acc;
    __syncthreads();
    if (threadIdx.x == 0) {
        float t = 0.f;
        #pragma unroll
        for (int i = 0; i < 8; i++) t += ssum[i];
        atomicAdd(&g_rowsum[b], t);
        __threadfence();
        unsigned old = atomicAdd(&g_done, 1u);
        slast = (old == gridDim.x - 1);
    }
    __syncthreads();
    if (slast && threadIdx.x < 32) {
        __threadfence();
        float w = g_rowsum[threadIdx.x] *
                  (16384.0f / (float)(NN - g_k[threadIdx.x]));
        #pragma unroll
        for (int o = 16; o; o >>= 1) w += __shfl_down_sync(0xffffffffu, w, o);
        if (threadIdx.x == 0 && out_size != BB * NN)
            out[0] = w / 33554432.0f;                // B*N*D
    }
}

extern "C" void kernel_launch(void* const* d_in, const int* in_sizes, int n_in,
                              void* d_out, int out_size) {
    const float* u_g   = (const float*)d_in[0];
    const float* lpt   = (const float*)d_in[1];
    const float* lph   = (const float*)d_in[2];
    const float* lpw   = (const float*)d_in[3];
    const float* u_k   = (const float*)d_in[4];
    const float* score = (const float*)d_in[5];
    float* out = (float*)d_out;

    cudaFuncSetAttribute(k_select,
                         cudaFuncAttributeMaxDynamicSharedMemorySize, 65536);

    k_keys<<<BB * NN / 256, 256>>>(u_g, lpt, lph, lpw);
    k_select<<<BB, 1024, 65536>>>(u_k);
    k_mask_final<<<BB * NN / 256, 256>>>(score, out, out_size);
}

// round 6
// speedup vs baseline: 1.2194x; 1.0651x over previous
#include <cuda_runtime.h>
#include <cstdint>

#define BB 32
#define NN 16384
#define DD 64

// Scratch (no allocations allowed)
__device__ uint32_t g_keys[BB * NN];             // 2MB monotonic keys
__device__ float    g_rowsum[BB];
__device__ int      g_k[BB];
__device__ unsigned g_visbits[BB * (NN / 32)];   // 64KB visibility bitmask
__device__ unsigned g_done;

__device__ __forceinline__ uint32_t ws_key(float u, float m) {
    float g = -logf(-logf(u));
    float ws = g + m;
    uint32_t bits = __float_as_uint(ws);
    return (bits & 0x80000000u) ? ~bits : (bits | 0x80000000u);
}

// ---------------------------------------------------------------------------
// Kernel A1: full-chip key computation, 4 elements/thread (4 independent
// logf chains -> ILP hides MUFU/latency), float4 loads and stores.
// ---------------------------------------------------------------------------
__global__ void __launch_bounds__(256) k_keys(
    const float* __restrict__ u_g, const float* __restrict__ lpt,
    const float* __restrict__ lph, const float* __restrict__ lpw)
{
    int tid4 = blockIdx.x * 256 + threadIdx.x;
    if (tid4 < BB) g_rowsum[tid4] = 0.f;
    if (tid4 == 0) g_done = 0u;
    int idx = tid4 * 4;                    // 4 consecutive elements
    int b = idx >> 14;
    int n = idx & (NN - 1);
    int t = n >> 10;
    int h = (n >> 5) & 31;
    int w = n & 31;                        // multiple of 4, same t/h for all 4

    float4 u = *(const float4*)(u_g + idx);
    float4 lw = *(const float4*)(lpw + b * 32 + w);
    float base = lpt[b * 16 + t] + lph[b * 32 + h];

    uint4 out;
    out.x = ws_key(u.x, base + lw.x);      // (lpt+lph)+lpw == ref association
    out.y = ws_key(u.y, base + lw.y);
    out.z = ws_key(u.z, base + lw.z);
    out.w = ws_key(u.w, base + lw.w);
    *(uint4*)(g_keys + idx) = out;
}

// ---------------------------------------------------------------------------
// Kernel A2: one CTA per row. Loads keys into registers (+smem shadow for the
// rare tie path), exact 4x8-bit radix select, emits visibility bitmask.
// ---------------------------------------------------------------------------
__global__ void __launch_bounds__(1024, 1) k_select(const float* __restrict__ u_k)
{
    extern __shared__ uint32_t skeys[];   // NN words (64KB)
    __shared__ unsigned hist[256];
    __shared__ unsigned suf[256];
    __shared__ uint32_t s_prefix;
    __shared__ int s_krem, s_eqcnt;

    int b = blockIdx.x;
    int tid = threadIdx.x;

    // k per row: rates = (u_k + b/31) % 1 ; k = clip(int(N*rates), 1, N-1)
    float r = u_k[0] + (float)b * (1.0f / 31.0f);
    r = r - floorf(r);
    int k = (int)(16384.0f * r);
    k = k < 1 ? 1 : (k > NN - 1 ? NN - 1 : k);
    if (tid == 0) g_k[b] = k;

    const uint32_t* __restrict__ keys = g_keys + ((size_t)b << 14);
    uint32_t key[16];
    #pragma unroll
    for (int s = 0; s < 16; s++) {
        uint32_t kk = keys[s * 1024 + tid];
        key[s] = kk;
        skeys[s * 1024 + tid] = kk;
    }
    __syncthreads();

    // 4-pass radix select on register-resident keys
    uint32_t prefix = 0, pmask = 0;
    int krem = k;
    for (int pass = 0; pass < 4; pass++) {
        int shift = 24 - 8 * pass;
        if (tid < 256) hist[tid] = 0;
        __syncthreads();
        #pragma unroll
        for (int s = 0; s < 16; s++) {
            uint32_t kk = key[s];
            if ((kk & pmask) == prefix)
                atomicAdd(&hist[(kk >> shift) & 255u], 1u);
        }
        __syncthreads();
        if (tid < 256) suf[tid] = hist[tid];
        __syncthreads();
        for (int d = 1; d < 256; d <<= 1) {       // inclusive suffix sums
            unsigned v = 0;
            if (tid < 256) { v = suf[tid]; if (tid + d < 256) v += suf[tid + d]; }
            __syncthreads();
            if (tid < 256) suf[tid] = v;
            __syncthreads();
        }
        if (tid < 256) {
            int above = (int)(suf[tid] - hist[tid]);   // strictly larger keys
            if (above < krem && krem <= (int)suf[tid]) {
                s_prefix = prefix | ((uint32_t)tid << shift);
                s_krem = krem - above;
                if (pass == 3) s_eqcnt = (int)hist[tid];
            }
        }
        __syncthreads();
        prefix = s_prefix;
        krem = s_krem;
        pmask |= (0xFFu << shift);
        __syncthreads();
    }

    uint32_t thr = prefix;
    int eqcnt = s_eqcnt;

    // Visibility -> bitmask (one ballot word per 32 consecutive tokens)
    #pragma unroll
    for (int s = 0; s < 16; s++) {
        uint32_t kk = key[s];
        bool vis;
        if (kk > thr) vis = true;
        else if (kk < thr) vis = false;
        else if (eqcnt <= krem) vis = true;          // all ties fit in top-k
        else {
            // rare tie path: stable rank by index among equals (from smem)
            int n = s * 1024 + tid;
            int cnt = 0;
            for (int i = 0; i < n; i++) cnt += (skeys[i] == thr);
            vis = cnt < krem;
        }
        unsigned m = __ballot_sync(0xffffffffu, vis);
        if ((tid & 31) == 0)
            g_visbits[(b << 9) + ((s * 1024 + tid) >> 5)] = m;
    }
}

// ---------------------------------------------------------------------------
// Kernel B: full-chip masked score reduction. Half-warp per token row:
// 16 predicated LDG.128 per warp (lanes 0-15 -> row 2jj, lanes 16-31 ->
// row 2jj+1). Blocks round-robin over rows for load balance.
// Last block computes the rate-corrected loss.
// ---------------------------------------------------------------------------
__global__ void __launch_bounds__(256) k_mask_final(
    const float* __restrict__ score, float* __restrict__ out, int out_size)
{
    __shared__ float ssum[8];
    __shared__ bool slast;
    int g = blockIdx.x;
    int b = g & 31;
    int chunk = g >> 5;                              // 0..63
    int warp = threadIdx.x >> 5, lane = threadIdx.x & 31;
    int tok0 = (b << 14) + chunk * 256 + warp * 32;

    unsigned visword = g_visbits[tok0 >> 5];

    if (out_size >= BB * NN) {
        int off = (out_size > BB * NN) ? 1 : 0;      // loss slot first
        out[off + tok0 + lane] = ((visword >> lane) & 1u) ? 1.0f : 0.0f;
    }

    // lanes 0-15 handle even token of each pair, lanes 16-31 the odd one.
    int sub = lane >> 4;                             // 0 or 1
    const float4* __restrict__ rowsq =
        (const float4*)score + (((size_t)(tok0 + sub)) << 4) + (lane & 15);

    float a0 = 0.f, a1 = 0.f, a2 = 0.f, a3 = 0.f;
    #pragma unroll
    for (int jj = 0; jj < 16; jj += 4) {
        float4 z = make_float4(0.f, 0.f, 0.f, 0.f);
        float4 v0 = z, v1 = z, v2 = z, v3 = z;
        if (!((visword >> (2 * (jj + 0) + sub)) & 1u)) v0 = rowsq[(jj + 0) * 32];
        if (!((visword >> (2 * (jj + 1) + sub)) & 1u)) v1 = rowsq[(jj + 1) * 32];
        if (!((visword >> (2 * (jj + 2) + sub)) & 1u)) v2 = rowsq[(jj + 2) * 32];
        if (!((visword >> (2 * (jj + 3) + sub)) & 1u)) v3 = rowsq[(jj + 3) * 32];
        a0 += (v0.x + v0.y) + (v0.z + v0.w);
        a1 += (v1.x + v1.y) + (v1.z + v1.w);
        a2 += (v2.x + v2.y) + (v2.z + v2.w);
        a3 += (v3.x + v3.y) + (v3.z + v3.w);
    }
    float acc = (a0 + a1) + (a2 + a3);
    #pragma unroll
    for (int o = 16; o; o >>= 1) acc += __shfl_down_sync(0xffffffffu, acc, o);
    if (lane == 0) ssum[warp] = acc;
    __syncthreads();
    if (threadIdx.x == 0) {
        float t = 0.f;
        #pragma unroll
        for (int i = 0; i < 8; i++) t += ssum[i];
        atomicAdd(&g_rowsum[b], t);
        __threadfence();
        unsigned old = atomicAdd(&g_done, 1u);
        slast = (old == gridDim.x - 1);
    }
    __syncthreads();
    if (slast && threadIdx.x < 32) {
        __threadfence();
        float w = g_rowsum[threadIdx.x] *
                  (16384.0f / (float)(NN - g_k[threadIdx.x]));
        #pragma unroll
        for (int o = 16; o; o >>= 1) w += __shfl_down_sync(0xffffffffu, w, o);
        if (threadIdx.x == 0 && out_size != BB * NN)
            out[0] = w / 33554432.0f;                // B*N*D
    }
}

extern "C" void kernel_launch(void* const* d_in, const int* in_sizes, int n_in,
                              void* d_out, int out_size) {
    const float* u_g   = (const float*)d_in[0];
    const float* lpt   = (const float*)d_in[1];
    const float* lph   = (const float*)d_in[2];
    const float* lpw   = (const float*)d_in[3];
    const float* u_k   = (const float*)d_in[4];
    const float* score = (const float*)d_in[5];
    float* out = (float*)d_out;

    cudaFuncSetAttribute(k_select,
                         cudaFuncAttributeMaxDynamicSharedMemorySize, 65536);

    k_keys<<<BB * NN / 1024, 256>>>(u_g, lpt, lph, lpw);
    k_select<<<BB, 1024, 65536>>>(u_k);
    k_mask_final<<<BB * NN / 256, 256>>>(score, out, out_size);
}